// round 16
// baseline (speedup 1.0000x reference)
#include <cuda_runtime.h>
#include <cuda_bf16.h>
#include <math.h>
#include <stdint.h>

#define BB 8
#define NN 1024
#define DD 256
#define HH 8
#define HD 32
#define ROWS (BB*NN)          // 8192
#define ELEMS (ROWS*DD)       // 2097152

typedef unsigned long long u64;

// -------- scratch (static device globals; no allocation) --------
__device__ float g_o[ELEMS];      // attention output

__device__ __nv_bfloat16 g_qih[ELEMS];   // input splits (GEMM A operands)
__device__ __nv_bfloat16 g_qil[ELEMS];
__device__ __nv_bfloat16 g_kih[ELEMS];
__device__ __nv_bfloat16 g_kil[ELEMS];
__device__ __nv_bfloat16 g_th[ELEMS];    // ln0 out split (also MLP residual source)
__device__ __nv_bfloat16 g_tl[ELEMS];

// attention operand splits (produced by projection epilogues)
__device__ __nv_bfloat16 g_aqh[ELEMS]; __device__ __nv_bfloat16 g_aql[ELEMS];
__device__ __nv_bfloat16 g_akh[ELEMS]; __device__ __nv_bfloat16 g_akl[ELEMS];
__device__ __nv_bfloat16 g_avh[ELEMS]; __device__ __nv_bfloat16 g_avl[ELEMS];

#define WSZ (DD*DD)
__device__ __nv_bfloat16 g_wqh[WSZ]; __device__ __nv_bfloat16 g_wql[WSZ];
__device__ __nv_bfloat16 g_wkh[WSZ]; __device__ __nv_bfloat16 g_wkl[WSZ];
__device__ __nv_bfloat16 g_wvh[WSZ]; __device__ __nv_bfloat16 g_wvl[WSZ];
__device__ __nv_bfloat16 g_woh[WSZ]; __device__ __nv_bfloat16 g_wol[WSZ];

// ---------- helpers ----------
__device__ __forceinline__ void ldmx4(uint32_t* r, uint32_t addr) {
    asm volatile("ldmatrix.sync.aligned.m8n8.x4.shared.b16 {%0,%1,%2,%3}, [%4];"
                 : "=r"(r[0]), "=r"(r[1]), "=r"(r[2]), "=r"(r[3]) : "r"(addr));
}
__device__ __forceinline__ void ldmx4t(uint32_t* r, uint32_t addr) {
    asm volatile("ldmatrix.sync.aligned.m8n8.x4.trans.shared.b16 {%0,%1,%2,%3}, [%4];"
                 : "=r"(r[0]), "=r"(r[1]), "=r"(r[2]), "=r"(r[3]) : "r"(addr));
}
__device__ __forceinline__ void mma_bf16(float* c, const uint32_t* a, uint32_t b0, uint32_t b1) {
    asm volatile(
        "mma.sync.aligned.m16n8k16.row.col.f32.bf16.bf16.f32 "
        "{%0,%1,%2,%3}, {%4,%5,%6,%7}, {%8,%9}, {%0,%1,%2,%3};"
        : "+f"(c[0]), "+f"(c[1]), "+f"(c[2]), "+f"(c[3])
        : "r"(a[0]), "r"(a[1]), "r"(a[2]), "r"(a[3]), "r"(b0), "r"(b1));
}
__device__ __forceinline__ uint32_t packbf(float lo, float hi) {
    uint32_t r;
    asm("cvt.rn.bf16x2.f32 %0, %1, %2;" : "=r"(r) : "f"(hi), "f"(lo));
    return r;
}
__device__ __forceinline__ float bflo_f(uint32_t p) { return __uint_as_float(p << 16); }
__device__ __forceinline__ float bfhi_f(uint32_t p) { return __uint_as_float(p & 0xFFFF0000u); }

__device__ __forceinline__ void cpa16(uint32_t saddr, const void* g) {
    asm volatile("cp.async.cg.shared.global [%0], [%1], 16;" :: "r"(saddr), "l"(g));
}
__device__ __forceinline__ void cpa_commit() {
    asm volatile("cp.async.commit_group;" ::: "memory");
}
template<int N>
__device__ __forceinline__ void cpa_wait() {
    asm volatile("cp.async.wait_group %0;" :: "n"(N) : "memory");
}

// ================= fused prep: input splits (Q,K) + weight transpose-splits =============
__global__ void __launch_bounds__(256) prep_kernel(
    const float4* __restrict__ Q, const float4* __restrict__ K, int n4,
    const float* __restrict__ Wq, const float* __restrict__ Wk,
    const float* __restrict__ Wv, const float* __restrict__ Wo)
{
    const int bx = blockIdx.x;
    if (bx < 2048) {
        const int sel = bx >> 10;
        const float4* x = sel ? K : Q;
        uint2* hi = sel ? (uint2*)g_kih : (uint2*)g_qih;
        uint2* lo = sel ? (uint2*)g_kil : (uint2*)g_qil;
        int base = (bx & 1023) * 512 + threadIdx.x;
        #pragma unroll
        for (int it = 0; it < 2; it++) {
            int i = base + it * 256;
            if (i < n4) {
                float4 v = x[i];
                uint32_t h0 = packbf(v.x, v.y), h1 = packbf(v.z, v.w);
                uint32_t l0 = packbf(v.x - bflo_f(h0), v.y - bfhi_f(h0));
                uint32_t l1 = packbf(v.z - bflo_f(h1), v.w - bfhi_f(h1));
                uint2 hu, lu; hu.x = h0; hu.y = h1; lu.x = l0; lu.y = l1;
                hi[i] = hu; lo[i] = lu;
            }
        }
        return;
    }
    __shared__ float tile[32][33];
    const int bid = bx - 2048;
    const int wsel = bid >> 6, bxx = bid & 63;
    const float* W; __nv_bfloat16 *th, *tl;
    switch (wsel) {
        case 0: W = Wq; th = g_wqh; tl = g_wql; break;
        case 1: W = Wk; th = g_wkh; tl = g_wkl; break;
        case 2: W = Wv; th = g_wvh; tl = g_wvl; break;
        default: W = Wo; th = g_woh; tl = g_wol; break;
    }
    const int tx = threadIdx.x & 31, ty = threadIdx.x >> 5;
    const int tR = (bxx & 7) * 32, tC = (bxx >> 3) * 32;
    #pragma unroll
    for (int j = 0; j < 4; j++)
        tile[ty + j * 8][tx] = W[(tR + ty + j * 8) * DD + tC + tx];
    __syncthreads();
    #pragma unroll
    for (int j = 0; j < 4; j++) {
        int n = tC + ty + j * 8, k = tR + tx;
        float w = tile[tx][ty + j * 8];
        __nv_bfloat16 h = __float2bfloat16(w);
        th[n * DD + k] = h;
        tl[n * DD + k] = __float2bfloat16(w - __bfloat162float(h));
    }
}

// ================= projection GEMM: 64x256 full-row tiles (mlp_ln-style loop) ===========
#define PSTR 40
#define MA_TILE (64 * PSTR * 2)       // 5120 B
#define MB_TILE (256 * PSTR * 2)      // 20480 B
#define MSTAGE (2 * MA_TILE + 2 * MB_TILE)   // 51200 B
#define MLP_SMEM (2 * MSTAGE)                // 102400 B
#define NCH 8

__global__ void __launch_bounds__(256, 2) proj_kernel(
    const float* __restrict__ bq, const float* __restrict__ bk,
    const float* __restrict__ bv, const int* __restrict__ lengths)
{
    extern __shared__ char smc[];
    const int tid = threadIdx.x, wid = tid >> 5, lane = tid & 31;
    const int brow = blockIdx.x * 64;
    const int wm = wid & 1, wn = wid >> 1;

    const __nv_bfloat16 *Ah_, *Al_, *Bh_, *Bl_;
    const float *bias;
    __nv_bfloat16 *Ch, *Cl;
    switch (blockIdx.y) {
        case 0:  Ah_ = g_qih; Al_ = g_qil; Bh_ = g_wqh; Bl_ = g_wql;
                 bias = bq; Ch = g_aqh; Cl = g_aql; break;
        case 1:  Ah_ = g_kih; Al_ = g_kil; Bh_ = g_wkh; Bl_ = g_wkl;
                 bias = bk; Ch = g_akh; Cl = g_akl; break;
        default: Ah_ = g_kih; Al_ = g_kil; Bh_ = g_wvh; Bl_ = g_wvl;
                 bias = bv; Ch = g_avh; Cl = g_avl; break;
    }

    const int blen = lengths[brow >> 10];
    if ((brow & 1023) >= blen) {
        uint4 zu = make_uint4(0u, 0u, 0u, 0u);
        #pragma unroll
        for (int i = 0; i < 8; i++) {       // 64 rows x 32 uint4 (2 arrays x 16)
            int idx = tid + i * 256;
            int r = idx >> 5, half = (idx >> 4) & 1, c8 = idx & 15;
            __nv_bfloat16* dst = half ? Cl : Ch;
            *(uint4*)&dst[(size_t)(brow + r) * DD + c8 * 8] = zu;
        }
        return;
    }

    const uint32_t sbu = (uint32_t)__cvta_generic_to_shared(smc);
    const int ldr4 = tid >> 2;
    const int ldc4 = tid & 3;

    auto load_chunk = [&](int ch, int st) {
        const int kc0 = ch * 32;
        const uint32_t s0 = sbu + st * MSTAGE;
        {
            size_t ga = (size_t)(brow + ldr4) * DD + kc0 + ldc4 * 8;
            uint32_t so = (uint32_t)(ldr4 * PSTR + ldc4 * 8) * 2u;
            cpa16(s0 + so, Ah_ + ga);
            cpa16(s0 + MA_TILE + so, Al_ + ga);
        }
        #pragma unroll
        for (int i = 0; i < 4; i++) {
            int r = ldr4 + i * 64;
            size_t gb = (size_t)r * DD + kc0 + ldc4 * 8;
            uint32_t so = (uint32_t)(r * PSTR + ldc4 * 8) * 2u;
            cpa16(s0 + 2 * MA_TILE + so, Bh_ + gb);
            cpa16(s0 + 2 * MA_TILE + MB_TILE + so, Bl_ + gb);
        }
    };

    float acc[2][8][4];
    #pragma unroll
    for (int i = 0; i < 2; i++)
        #pragma unroll
        for (int j = 0; j < 8; j++)
            #pragma unroll
            for (int p = 0; p < 4; p++) acc[i][j][p] = 0.f;

    const int aRow = wm * 32 + (lane & 15);
    const int aK   = (lane >> 4) * 8;
    const int bRow = wn * 64 + (lane & 7) + (lane >> 4) * 8;
    const int bK   = ((lane >> 3) & 1) * 8;

    load_chunk(0, 0);
    cpa_commit();

    for (int ch = 0; ch < NCH; ch++) {
        if (ch < NCH - 1) { load_chunk(ch + 1, (ch + 1) & 1); cpa_commit(); }
        if (ch < NCH - 1) cpa_wait<1>(); else cpa_wait<0>();
        __syncthreads();

        const uint32_t stb = sbu + (ch & 1) * MSTAGE;
        const uint32_t bAh = stb, bAl = stb + MA_TILE;
        const uint32_t bBh = stb + 2 * MA_TILE, bBl = bBh + MB_TILE;

        #pragma unroll
        for (int ks = 0; ks < 2; ks++) {
            const int kk = ks * 16;
            uint32_t ah[2][4], al[2][4], bh[4][4], bl[4][4];
            #pragma unroll
            for (int mi = 0; mi < 2; mi++) {
                uint32_t off = (uint32_t)((aRow + mi * 16) * PSTR + kk + aK) * 2u;
                ldmx4(ah[mi], bAh + off);
                ldmx4(al[mi], bAl + off);
            }
            #pragma unroll
            for (int n2 = 0; n2 < 4; n2++) {
                uint32_t off = (uint32_t)((bRow + n2 * 16) * PSTR + kk + bK) * 2u;
                ldmx4(bh[n2], bBh + off);
                ldmx4(bl[n2], bBl + off);
            }
            #pragma unroll
            for (int mi = 0; mi < 2; mi++)
                #pragma unroll
                for (int ni = 0; ni < 8; ni++) {
                    uint32_t bh0 = bh[ni >> 1][(ni & 1) * 2], bh1 = bh[ni >> 1][(ni & 1) * 2 + 1];
                    uint32_t bl0 = bl[ni >> 1][(ni & 1) * 2], bl1 = bl[ni >> 1][(ni & 1) * 2 + 1];
                    mma_bf16(acc[mi][ni], ah[mi], bh0, bh1);
                    mma_bf16(acc[mi][ni], ah[mi], bl0, bl1);
                    mma_bf16(acc[mi][ni], al[mi], bh0, bh1);
                }
        }
        __syncthreads();
    }

    #pragma unroll
    for (int mi = 0; mi < 2; mi++) {
        int r0 = brow + wm * 32 + mi * 16 + (lane >> 2);
        int r1 = r0 + 8;
        #pragma unroll
        for (int ni = 0; ni < 8; ni++) {
            int col = wn * 64 + ni * 8 + (lane & 3) * 2;
            float b0 = bias[col], b1 = bias[col + 1];
            float c0 = acc[mi][ni][0] + b0, c1 = acc[mi][ni][1] + b1;
            float c2 = acc[mi][ni][2] + b0, c3 = acc[mi][ni][3] + b1;
            if ((r0 & 1023) >= blen) { c0 = 0.f; c1 = 0.f; }
            if ((r1 & 1023) >= blen) { c2 = 0.f; c3 = 0.f; }
            uint32_t h0 = packbf(c0, c1), h1 = packbf(c2, c3);
            uint32_t l0 = packbf(c0 - bflo_f(h0), c1 - bfhi_f(h0));
            uint32_t l1 = packbf(c2 - bflo_f(h1), c3 - bfhi_f(h1));
            *(uint32_t*)&Ch[(size_t)r0 * DD + col] = h0;
            *(uint32_t*)&Cl[(size_t)r0 * DD + col] = l0;
            *(uint32_t*)&Ch[(size_t)r1 * DD + col] = h1;
            *(uint32_t*)&Cl[(size_t)r1 * DD + col] = l1;
        }
    }
}

// ================= fused MLP GEMM + residual + relu + LayerNorm1 → d_out (verified) =====
__global__ void __launch_bounds__(256, 2) mlp_ln_kernel(
    const float* __restrict__ bo, const float* __restrict__ g1,
    const float* __restrict__ b1, float* __restrict__ out)
{
    extern __shared__ char smc[];
    const int tid = threadIdx.x, wid = tid >> 5, lane = tid & 31;
    const int brow = blockIdx.x * 64;
    const int wm = wid & 1, wn = wid >> 1;

    const uint32_t sbu = (uint32_t)__cvta_generic_to_shared(smc);
    const int ldr4 = tid >> 2;
    const int ldc4 = tid & 3;

    auto load_chunk = [&](int ch, int st) {
        const int kc0 = ch * 32;
        const uint32_t s0 = sbu + st * MSTAGE;
        {
            size_t ga = (size_t)(brow + ldr4) * DD + kc0 + ldc4 * 8;
            uint32_t so = (uint32_t)(ldr4 * PSTR + ldc4 * 8) * 2u;
            cpa16(s0 + so, g_th + ga);
            cpa16(s0 + MA_TILE + so, g_tl + ga);
        }
        #pragma unroll
        for (int i = 0; i < 4; i++) {
            int r = ldr4 + i * 64;
            size_t gb = (size_t)r * DD + kc0 + ldc4 * 8;
            uint32_t so = (uint32_t)(r * PSTR + ldc4 * 8) * 2u;
            cpa16(s0 + 2 * MA_TILE + so, g_woh + gb);
            cpa16(s0 + 2 * MA_TILE + MB_TILE + so, g_wol + gb);
        }
    };

    float acc[2][8][4];
    #pragma unroll
    for (int i = 0; i < 2; i++)
        #pragma unroll
        for (int j = 0; j < 8; j++)
            #pragma unroll
            for (int p = 0; p < 4; p++) acc[i][j][p] = 0.f;

    const int aRow = wm * 32 + (lane & 15);
    const int aK   = (lane >> 4) * 8;
    const int bRow = wn * 64 + (lane & 7) + (lane >> 4) * 8;
    const int bK   = ((lane >> 3) & 1) * 8;

    load_chunk(0, 0);
    cpa_commit();

    for (int ch = 0; ch < NCH; ch++) {
        if (ch < NCH - 1) { load_chunk(ch + 1, (ch + 1) & 1); cpa_commit(); }
        if (ch < NCH - 1) cpa_wait<1>(); else cpa_wait<0>();
        __syncthreads();

        const uint32_t stb = sbu + (ch & 1) * MSTAGE;
        const uint32_t bAh = stb, bAl = stb + MA_TILE;
        const uint32_t bBh = stb + 2 * MA_TILE, bBl = bBh + MB_TILE;

        #pragma unroll
        for (int ks = 0; ks < 2; ks++) {
            const int kk = ks * 16;
            uint32_t ah[2][4], al[2][4], bh[4][4], bl[4][4];
            #pragma unroll
            for (int mi = 0; mi < 2; mi++) {
                uint32_t off = (uint32_t)((aRow + mi * 16) * PSTR + kk + aK) * 2u;
                ldmx4(ah[mi], bAh + off);
                ldmx4(al[mi], bAl + off);
            }
            #pragma unroll
            for (int n2 = 0; n2 < 4; n2++) {
                uint32_t off = (uint32_t)((bRow + n2 * 16) * PSTR + kk + bK) * 2u;
                ldmx4(bh[n2], bBh + off);
                ldmx4(bl[n2], bBl + off);
            }
            #pragma unroll
            for (int mi = 0; mi < 2; mi++)
                #pragma unroll
                for (int ni = 0; ni < 8; ni++) {
                    uint32_t bh0 = bh[ni >> 1][(ni & 1) * 2], bh1 = bh[ni >> 1][(ni & 1) * 2 + 1];
                    uint32_t bl0 = bl[ni >> 1][(ni & 1) * 2], bl1 = bl[ni >> 1][(ni & 1) * 2 + 1];
                    mma_bf16(acc[mi][ni], ah[mi], bh0, bh1);
                    mma_bf16(acc[mi][ni], ah[mi], bl0, bl1);
                    mma_bf16(acc[mi][ni], al[mi], bh0, bh1);
                }
        }
        __syncthreads();
    }

    float* sums = (float*)smc;
    float* sqs  = sums + 64 * 4;

    #pragma unroll
    for (int mi = 0; mi < 2; mi++) {
        int r0 = brow + wm * 32 + mi * 16 + (lane >> 2);
        int r1 = r0 + 8;
        float s0 = 0.f, q0 = 0.f, s1 = 0.f, q1 = 0.f;
        #pragma unroll
        for (int ni = 0; ni < 8; ni++) {
            int col = wn * 64 + ni * 8 + (lane & 3) * 2;
            float b0 = bo[col], b1v = bo[col + 1];
            uint32_t xh0 = *(const uint32_t*)&g_th[(size_t)r0 * DD + col];
            uint32_t xl0 = *(const uint32_t*)&g_tl[(size_t)r0 * DD + col];
            uint32_t xh1 = *(const uint32_t*)&g_th[(size_t)r1 * DD + col];
            uint32_t xl1 = *(const uint32_t*)&g_tl[(size_t)r1 * DD + col];
            float c0 = (bflo_f(xh0) + bflo_f(xl0)) + fmaxf(acc[mi][ni][0] + b0, 0.f);
            float c1 = (bfhi_f(xh0) + bfhi_f(xl0)) + fmaxf(acc[mi][ni][1] + b1v, 0.f);
            float c2 = (bflo_f(xh1) + bflo_f(xl1)) + fmaxf(acc[mi][ni][2] + b0, 0.f);
            float c3 = (bfhi_f(xh1) + bfhi_f(xl1)) + fmaxf(acc[mi][ni][3] + b1v, 0.f);
            acc[mi][ni][0] = c0; acc[mi][ni][1] = c1;
            acc[mi][ni][2] = c2; acc[mi][ni][3] = c3;
            s0 += c0 + c1; q0 += c0 * c0 + c1 * c1;
            s1 += c2 + c3; q1 += c2 * c2 + c3 * c3;
        }
        s0 += __shfl_xor_sync(0xFFFFFFFFu, s0, 1); s0 += __shfl_xor_sync(0xFFFFFFFFu, s0, 2);
        q0 += __shfl_xor_sync(0xFFFFFFFFu, q0, 1); q0 += __shfl_xor_sync(0xFFFFFFFFu, q0, 2);
        s1 += __shfl_xor_sync(0xFFFFFFFFu, s1, 1); s1 += __shfl_xor_sync(0xFFFFFFFFu, s1, 2);
        q1 += __shfl_xor_sync(0xFFFFFFFFu, q1, 1); q1 += __shfl_xor_sync(0xFFFFFFFFu, q1, 2);
        if ((lane & 3) == 0) {
            int lr = wm * 32 + mi * 16 + (lane >> 2);
            sums[lr * 4 + wn] = s0; sqs[lr * 4 + wn] = q0;
            sums[(lr + 8) * 4 + wn] = s1; sqs[(lr + 8) * 4 + wn] = q1;
        }
    }
    __syncthreads();

    #pragma unroll
    for (int mi = 0; mi < 2; mi++) {
        int lr0 = wm * 32 + mi * 16 + (lane >> 2);
        int lr1 = lr0 + 8;
        float mu0 = (sums[lr0*4+0] + sums[lr0*4+1] + sums[lr0*4+2] + sums[lr0*4+3]) * (1.f/256.f);
        float mu1 = (sums[lr1*4+0] + sums[lr1*4+1] + sums[lr1*4+2] + sums[lr1*4+3]) * (1.f/256.f);
        float v0 = (sqs[lr0*4+0] + sqs[lr0*4+1] + sqs[lr0*4+2] + sqs[lr0*4+3]) * (1.f/256.f) - mu0 * mu0;
        float v1 = (sqs[lr1*4+0] + sqs[lr1*4+1] + sqs[lr1*4+2] + sqs[lr1*4+3]) * (1.f/256.f) - mu1 * mu1;
        float r0s = rsqrtf(v0 + 1e-5f);
        float r1s = rsqrtf(v1 + 1e-5f);
        int gr0 = brow + lr0, gr1 = brow + lr1;
        #pragma unroll
        for (int ni = 0; ni < 8; ni++) {
            int col = wn * 64 + ni * 8 + (lane & 3) * 2;
            float2 gg = *(const float2*)&g1[col];
            float2 bb = *(const float2*)&b1[col];
            float2 o0, o1;
            o0.x = (acc[mi][ni][0] - mu0) * r0s * gg.x + bb.x;
            o0.y = (acc[mi][ni][1] - mu0) * r0s * gg.y + bb.y;
            o1.x = (acc[mi][ni][2] - mu1) * r1s * gg.x + bb.x;
            o1.y = (acc[mi][ni][3] - mu1) * r1s * gg.y + bb.y;
            *(float2*)&out[(size_t)gr0 * DD + col] = o0;
            *(float2*)&out[(size_t)gr1 * DD + col] = o1;
        }
    }
}

// ================= HMMA attention: S-phase bf16x2 (QlKh dropped), PV bf16x3 ============
#define QSTR 56
#define KSTR 56
#define VSTR2 40
#define SM_QH 0
#define SM_QL (SM_QH + 128*QSTR*2)      // 14336
#define SM_ST0 (SM_QL + 128*QSTR*2)     // 28672
#define KBYTES (64*KSTR*2)              // 7168
#define VBYTES (64*VSTR2*2)             // 5120
#define STAGEA (2*KBYTES + 2*VBYTES)    // 24576
#define SM_ATTN2 (SM_ST0 + 2*STAGEA)    // 77824

__global__ void __launch_bounds__(256) attn_hmma_kernel(
    const int* __restrict__ lengths, float* __restrict__ o)
{
    extern __shared__ char smc[];
    const int qt = blockIdx.x, h = blockIdx.y, b = blockIdx.z;
    const int len = lengths[b];
    const int tid = threadIdx.x, w = tid >> 5, lane = tid & 31;

    if (qt * 128 >= len) {
        float4 z = make_float4(0.f, 0.f, 0.f, 0.f);
        #pragma unroll
        for (int i = 0; i < 4; i++) {
            int idx = tid + i * 256;
            int r = idx >> 3, c4 = idx & 7;
            *(float4*)&o[((size_t)b * NN + qt * 128 + r) * DD + h * HD + c4 * 4] = z;
        }
        return;
    }

    const uint32_t sb = (uint32_t)__cvta_generic_to_shared(smc);

    const int ldr = tid >> 2, ldc4 = tid & 3;
    auto load_tile = [&](int m0, int st) {
        int row = m0 + ldr; if (row >= len) row = len - 1;
        size_t g = ((size_t)b * NN + row) * DD + h * HD + ldc4 * 8;
        uint32_t s0 = sb + SM_ST0 + st * STAGEA;
        cpa16(s0 + (uint32_t)(ldr * KSTR + ldc4 * 8) * 2u,           g_akh + g);
        cpa16(s0 + KBYTES + (uint32_t)(ldr * KSTR + ldc4 * 8) * 2u,  g_akl + g);
        cpa16(s0 + 2*KBYTES + (uint32_t)(ldr * VSTR2 + ldc4 * 8) * 2u,          g_avh + g);
        cpa16(s0 + 2*KBYTES + VBYTES + (uint32_t)(ldr * VSTR2 + ldc4 * 8) * 2u, g_avl + g);
    };

    load_tile(0, 0);
    cpa_commit();

    {   // Q tile (128 x 32) hi/lo (lo kept for the residual reconstruction)
        const size_t gq = ((size_t)b * NN + qt * 128) * DD + h * HD;
        #pragma unroll
        for (int i = 0; i < 2; i++) {
            int idx = tid + i * 256;
            int r = idx >> 2, c4 = idx & 3;
            *(uint4*)(smc + SM_QH + (r * QSTR + c4 * 8) * 2) = *(const uint4*)(g_aqh + gq + (size_t)r * DD + c4 * 8);
            *(uint4*)(smc + SM_QL + (r * QSTR + c4 * 8) * 2) = *(const uint4*)(g_aql + gq + (size_t)r * DD + c4 * 8);
        }
    }
    __syncthreads();

    uint32_t qfh[2][4];
    {
        int row = w * 16 + (lane & 15);
        #pragma unroll
        for (int kt = 0; kt < 2; kt++) {
            uint32_t off = (uint32_t)(row * QSTR + kt * 16 + (lane >> 4) * 8) * 2u;
            ldmx4(qfh[kt], sb + SM_QH + off);
        }
    }

    float ofA[4][4], ofB[4][4];
    #pragma unroll
    for (int i = 0; i < 4; i++)
        #pragma unroll
        for (int p = 0; p < 4; p++) { ofA[i][p] = 0.f; ofB[i][p] = 0.f; }
    float es0a = 0.f, es0b = 0.f, es1a = 0.f, es1b = 0.f;

    const int kRow = (lane & 7) + ((lane >> 4) << 3);
    const int kColHalf = ((lane >> 3) & 1) * 8;
    const int vRow = lane & 15;
    const int vCol = (lane >> 4) * 8;

    int st = 0;
    for (int m0 = 0; m0 < len; m0 += 64, st ^= 1) {
        cpa_wait<0>();
        __syncthreads();
        if (m0 + 64 < len) { load_tile(m0 + 64, st ^ 1); cpa_commit(); }

        const uint32_t bKH = sb + SM_ST0 + st * STAGEA;
        const uint32_t bKL = bKH + KBYTES;
        const uint32_t bVH = bKH + 2 * KBYTES;
        const uint32_t bVL = bVH + VBYTES;

        // ---- S = Q K^T : QhKh + QhKl (QlKh dropped; err ~4e-4 on exp, << 1e-3 gate) ----
        float sf[8][4];
        #pragma unroll
        for (int i = 0; i < 8; i++)
            #pragma unroll
            for (int p = 0; p < 4; p++) sf[i][p] = 0.f;
        #pragma unroll
        for (int kt = 0; kt < 2; kt++) {
            #pragma unroll
            for (int g2 = 0; g2 < 4; g2++) {
                uint32_t off = (uint32_t)((g2 * 16 + kRow) * KSTR + kt * 16 + kColHalf) * 2u;
                uint32_t kbh[4], kbl[4];
                ldmx4(kbh, bKH + off);
                ldmx4(kbl, bKL + off);
                mma_bf16(sf[g2*2],   qfh[kt], kbh[0], kbh[1]);
                mma_bf16(sf[g2*2],   qfh[kt], kbl[0], kbl[1]);
                mma_bf16(sf[g2*2+1], qfh[kt], kbh[2], kbh[3]);
                mma_bf16(sf[g2*2+1], qfh[kt], kbl[2], kbl[3]);
            }
        }

        uint32_t ph[8], phb[8], pl[8], plb[8];
        if (m0 + 64 <= len) {
            #pragma unroll
            for (int ni = 0; ni < 8; ni++) {
                float e0 = __expf(sf[ni][0] * 0.0625f);
                float e1 = __expf(sf[ni][1] * 0.0625f);
                float e2 = __expf(sf[ni][2] * 0.0625f);
                float e3 = __expf(sf[ni][3] * 0.0625f);
                if (ni & 1) { es0b += e0 + e1; es1b += e2 + e3; }
                else        { es0a += e0 + e1; es1a += e2 + e3; }
                uint32_t h0 = packbf(e0, e1), h1 = packbf(e2, e3);
                ph[ni] = h0; phb[ni] = h1;
                pl[ni]  = packbf(e0 - bflo_f(h0), e1 - bfhi_f(h0));
                plb[ni] = packbf(e2 - bflo_f(h1), e3 - bfhi_f(h1));
            }
        } else {
            #pragma unroll
            for (int ni = 0; ni < 8; ni++) {
                int k0 = m0 + ni * 8 + ((lane & 3) << 1);
                float e0 = (k0     < len) ? __expf(sf[ni][0] * 0.0625f) : 0.f;
                float e1 = (k0 + 1 < len) ? __expf(sf[ni][1] * 0.0625f) : 0.f;
                float e2 = (k0     < len) ? __expf(sf[ni][2] * 0.0625f) : 0.f;
                float e3 = (k0 + 1 < len) ? __expf(sf[ni][3] * 0.0625f) : 0.f;
                if (ni & 1) { es0b += e0 + e1; es1b += e2 + e3; }
                else        { es0a += e0 + e1; es1a += e2 + e3; }
                uint32_t h0 = packbf(e0, e1), h1 = packbf(e2, e3);
                ph[ni] = h0; phb[ni] = h1;
                pl[ni]  = packbf(e0 - bflo_f(h0), e1 - bfhi_f(h0));
                plb[ni] = packbf(e2 - bflo_f(h1), e3 - bfhi_f(h1));
            }
        }

        #pragma unroll
        for (int kt2 = 0; kt2 < 4; kt2++) {
            uint32_t pa_h[4] = { ph[2*kt2], phb[2*kt2], ph[2*kt2+1], phb[2*kt2+1] };
            uint32_t pa_l[4] = { pl[2*kt2], plb[2*kt2], pl[2*kt2+1], plb[2*kt2+1] };
            #pragma unroll
            for (int g2 = 0; g2 < 2; g2++) {
                uint32_t off = (uint32_t)((kt2 * 16 + vRow) * VSTR2 + g2 * 16 + vCol) * 2u;
                uint32_t vbh[4], vbl[4];
                ldmx4t(vbh, bVH + off);
                ldmx4t(vbl, bVL + off);
                mma_bf16(ofA[g2*2],   pa_h, vbh[0], vbh[1]);
                mma_bf16(ofB[g2*2],   pa_h, vbl[0], vbl[1]);
                mma_bf16(ofA[g2*2+1], pa_h, vbh[2], vbh[3]);
                mma_bf16(ofB[g2*2+1], pa_h, vbl[2], vbl[3]);
                if (kt2 & 1) {
                    mma_bf16(ofA[g2*2],   pa_l, vbh[0], vbh[1]);
                    mma_bf16(ofB[g2*2+1], pa_l, vbh[2], vbh[3]);
                } else {
                    mma_bf16(ofB[g2*2],   pa_l, vbh[0], vbh[1]);
                    mma_bf16(ofA[g2*2+1], pa_l, vbh[2], vbh[3]);
                }
            }
        }
    }

    float es0 = es0a + es0b, es1 = es1a + es1b;
    es0 += __shfl_xor_sync(0xFFFFFFFFu, es0, 1);
    es0 += __shfl_xor_sync(0xFFFFFFFFu, es0, 2);
    es1 += __shfl_xor_sync(0xFFFFFFFFu, es1, 1);
    es1 += __shfl_xor_sync(0xFFFFFFFFu, es1, 2);
    const float inv0 = 1.f / (es0 + 1e-15f);
    const float inv1 = 1.f / (es1 + 1e-15f);

    const int n0 = qt * 128 + w * 16 + (lane >> 2);
    const int n1 = n0 + 8;
    const bool a0 = n0 < len, a1 = n1 < len;
    const int r0l = w * 16 + (lane >> 2);
    #pragma unroll
    for (int ni = 0; ni < 4; ni++) {
        int ci = ni * 8 + ((lane & 3) << 1);
        int col = h * HD + ci;
        uint32_t uh0 = *(uint32_t*)(smc + SM_QH + (r0l * QSTR + ci) * 2);
        uint32_t ul0 = *(uint32_t*)(smc + SM_QL + (r0l * QSTR + ci) * 2);
        uint32_t uh1 = *(uint32_t*)(smc + SM_QH + ((r0l + 8) * QSTR + ci) * 2);
        uint32_t ul1 = *(uint32_t*)(smc + SM_QL + ((r0l + 8) * QSTR + ci) * 2);
        float2 o0, o1;
        o0.x = a0 ? (bflo_f(uh0) + bflo_f(ul0) + (ofA[ni][0] + ofB[ni][0]) * inv0) : 0.f;
        o0.y = a0 ? (bfhi_f(uh0) + bfhi_f(ul0) + (ofA[ni][1] + ofB[ni][1]) * inv0) : 0.f;
        o1.x = a1 ? (bflo_f(uh1) + bflo_f(ul1) + (ofA[ni][2] + ofB[ni][2]) * inv1) : 0.f;
        o1.y = a1 ? (bfhi_f(uh1) + bfhi_f(ul1) + (ofA[ni][3] + ofB[ni][3]) * inv1) : 0.f;
        *(float2*)&o[((size_t)b * NN + n0) * DD + col] = o0;
        *(float2*)&o[((size_t)b * NN + n1) * DD + col] = o1;
    }
}

// ---------------- warp-per-row LayerNorm0 (verified round-15) ----------------
__global__ void __launch_bounds__(256) ln_kernel(
    const float* __restrict__ x, const float* __restrict__ g,
    const float* __restrict__ b,
    __nv_bfloat16* __restrict__ yh, __nv_bfloat16* __restrict__ yl)
{
    const int row = blockIdx.x * 8 + (threadIdx.x >> 5);
    const int lane = threadIdx.x & 31;
    const int c0 = lane * 8;

    float4 v0 = *(const float4*)&x[(size_t)row * DD + c0];
    float4 v1 = *(const float4*)&x[(size_t)row * DD + c0 + 4];

    float s = ((v0.x + v0.y) + (v0.z + v0.w)) + ((v1.x + v1.y) + (v1.z + v1.w));
    float q = ((v0.x*v0.x + v0.y*v0.y) + (v0.z*v0.z + v0.w*v0.w))
            + ((v1.x*v1.x + v1.y*v1.y) + (v1.z*v1.z + v1.w*v1.w));
    #pragma unroll
    for (int o = 16; o > 0; o >>= 1) {
        s += __shfl_xor_sync(0xFFFFFFFFu, s, o);
        q += __shfl_xor_sync(0xFFFFFFFFu, q, o);
    }
    const float mu = s * (1.f / 256.f);
    const float var = q * (1.f / 256.f) - mu * mu;
    const float r = rsqrtf(var + 1e-5f);

    float4 gg0 = *(const float4*)&g[c0], gg1 = *(const float4*)&g[c0 + 4];
    float4 bb0 = *(const float4*)&b[c0], bb1 = *(const float4*)&b[c0 + 4];
    float out[8];
    out[0] = (v0.x - mu) * r * gg0.x + bb0.x; out[1] = (v0.y - mu) * r * gg0.y + bb0.y;
    out[2] = (v0.z - mu) * r * gg0.z + bb0.z; out[3] = (v0.w - mu) * r * gg0.w + bb0.w;
    out[4] = (v1.x - mu) * r * gg1.x + bb1.x; out[5] = (v1.y - mu) * r * gg1.y + bb1.y;
    out[6] = (v1.z - mu) * r * gg1.z + bb1.z; out[7] = (v1.w - mu) * r * gg1.w + bb1.w;

    uint4 hv, lv;
    uint32_t h0 = packbf(out[0], out[1]); hv.x = h0;
    uint32_t h1 = packbf(out[2], out[3]); hv.y = h1;
    uint32_t h2 = packbf(out[4], out[5]); hv.z = h2;
    uint32_t h3 = packbf(out[6], out[7]); hv.w = h3;
    lv.x = packbf(out[0] - bflo_f(h0), out[1] - bfhi_f(h0));
    lv.y = packbf(out[2] - bflo_f(h1), out[3] - bfhi_f(h1));
    lv.z = packbf(out[4] - bflo_f(h2), out[5] - bfhi_f(h2));
    lv.w = packbf(out[6] - bflo_f(h3), out[7] - bfhi_f(h3));
    *(uint4*)&yh[(size_t)row * DD + c0] = hv;
    *(uint4*)&yl[(size_t)row * DD + c0] = lv;
}

// ---------------- launch ----------------
extern "C" void kernel_launch(void* const* d_in, const int* in_sizes, int n_in,
                              void* d_out, int out_size)
{
    const float* Q       = (const float*)d_in[0];
    const float* K       = (const float*)d_in[1];
    const int*   lengths = (const int*)  d_in[2];
    const float* Wq      = (const float*)d_in[3];
    const float* bq      = (const float*)d_in[4];
    const float* Wk      = (const float*)d_in[5];
    const float* bk      = (const float*)d_in[6];
    const float* Wv      = (const float*)d_in[7];
    const float* bv      = (const float*)d_in[8];
    const float* Wo      = (const float*)d_in[9];
    const float* bo      = (const float*)d_in[10];
    const float* g0      = (const float*)d_in[11];
    const float* b0      = (const float*)d_in[12];
    const float* g1      = (const float*)d_in[13];
    const float* b1      = (const float*)d_in[14];

    float *so;
    cudaGetSymbolAddress((void**)&so, g_o);
    __nv_bfloat16 *th, *tl;
    cudaGetSymbolAddress((void**)&th, g_th);
    cudaGetSymbolAddress((void**)&tl, g_tl);

    static int cfg = 0;
    if (!cfg) {
        cudaFuncSetAttribute(proj_kernel, cudaFuncAttributeMaxDynamicSharedMemorySize, MLP_SMEM);
        cudaFuncSetAttribute(mlp_ln_kernel, cudaFuncAttributeMaxDynamicSharedMemorySize, MLP_SMEM);
        cudaFuncSetAttribute(attn_hmma_kernel, cudaFuncAttributeMaxDynamicSharedMemorySize, SM_ATTN2);
        cfg = 1;
    }

    const int n4 = ELEMS / 4;
    prep_kernel<<<2048 + 256, 256>>>((const float4*)Q, (const float4*)K, n4, Wq, Wk, Wv, Wo);

    proj_kernel<<<dim3(ROWS / 64, 3), 256, MLP_SMEM>>>(bq, bk, bv, lengths);

    attn_hmma_kernel<<<dim3(NN / 128, HH, BB), 256, SM_ATTN2>>>(lengths, so);

    ln_kernel<<<ROWS / 8, 256>>>(so, g0, b0, th, tl);

    mlp_ln_kernel<<<ROWS / 64, 256, MLP_SMEM>>>(bo, g1, b1, (float*)d_out);
}

// round 17
// speedup vs baseline: 1.0249x; 1.0249x over previous
#include <cuda_runtime.h>
#include <cuda_bf16.h>
#include <math.h>
#include <stdint.h>

#define BB 8
#define NN 1024
#define DD 256
#define HH 8
#define HD 32
#define ROWS (BB*NN)          // 8192
#define ELEMS (ROWS*DD)       // 2097152

typedef unsigned long long u64;

// -------- scratch (static device globals; no allocation) --------
__device__ float g_o[ELEMS];      // attention output

__device__ __nv_bfloat16 g_th[ELEMS];    // ln0 out split (also MLP residual source)
__device__ __nv_bfloat16 g_tl[ELEMS];

// attention operand splits (produced by projection epilogues)
__device__ __nv_bfloat16 g_aqh[ELEMS]; __device__ __nv_bfloat16 g_aql[ELEMS];
__device__ __nv_bfloat16 g_akh[ELEMS]; __device__ __nv_bfloat16 g_akl[ELEMS];
__device__ __nv_bfloat16 g_avh[ELEMS]; __device__ __nv_bfloat16 g_avl[ELEMS];

#define WSZ (DD*DD)
__device__ __nv_bfloat16 g_wqh[WSZ]; __device__ __nv_bfloat16 g_wql[WSZ];
__device__ __nv_bfloat16 g_wkh[WSZ]; __device__ __nv_bfloat16 g_wkl[WSZ];
__device__ __nv_bfloat16 g_wvh[WSZ]; __device__ __nv_bfloat16 g_wvl[WSZ];
__device__ __nv_bfloat16 g_woh[WSZ]; __device__ __nv_bfloat16 g_wol[WSZ];

// ---------- helpers ----------
__device__ __forceinline__ void ldmx4(uint32_t* r, uint32_t addr) {
    asm volatile("ldmatrix.sync.aligned.m8n8.x4.shared.b16 {%0,%1,%2,%3}, [%4];"
                 : "=r"(r[0]), "=r"(r[1]), "=r"(r[2]), "=r"(r[3]) : "r"(addr));
}
__device__ __forceinline__ void ldmx4t(uint32_t* r, uint32_t addr) {
    asm volatile("ldmatrix.sync.aligned.m8n8.x4.trans.shared.b16 {%0,%1,%2,%3}, [%4];"
                 : "=r"(r[0]), "=r"(r[1]), "=r"(r[2]), "=r"(r[3]) : "r"(addr));
}
__device__ __forceinline__ void mma_bf16(float* c, const uint32_t* a, uint32_t b0, uint32_t b1) {
    asm volatile(
        "mma.sync.aligned.m16n8k16.row.col.f32.bf16.bf16.f32 "
        "{%0,%1,%2,%3}, {%4,%5,%6,%7}, {%8,%9}, {%0,%1,%2,%3};"
        : "+f"(c[0]), "+f"(c[1]), "+f"(c[2]), "+f"(c[3])
        : "r"(a[0]), "r"(a[1]), "r"(a[2]), "r"(a[3]), "r"(b0), "r"(b1));
}
__device__ __forceinline__ uint32_t packbf(float lo, float hi) {
    uint32_t r;
    asm("cvt.rn.bf16x2.f32 %0, %1, %2;" : "=r"(r) : "f"(hi), "f"(lo));
    return r;
}
__device__ __forceinline__ float bflo_f(uint32_t p) { return __uint_as_float(p << 16); }
__device__ __forceinline__ float bfhi_f(uint32_t p) { return __uint_as_float(p & 0xFFFF0000u); }

__device__ __forceinline__ void cpa16(uint32_t saddr, const void* g) {
    asm volatile("cp.async.cg.shared.global [%0], [%1], 16;" :: "r"(saddr), "l"(g));
}
__device__ __forceinline__ void cpa_commit() {
    asm volatile("cp.async.commit_group;" ::: "memory");
}
template<int N>
__device__ __forceinline__ void cpa_wait() {
    asm volatile("cp.async.wait_group %0;" :: "n"(N) : "memory");
}

// ================= prep: weight transpose-splits only =================
__global__ void __launch_bounds__(256) prep_kernel(
    const float* __restrict__ Wq, const float* __restrict__ Wk,
    const float* __restrict__ Wv, const float* __restrict__ Wo)
{
    __shared__ float tile[32][33];
    const int wsel = blockIdx.x >> 6, bxx = blockIdx.x & 63;
    const float* W; __nv_bfloat16 *th, *tl;
    switch (wsel) {
        case 0: W = Wq; th = g_wqh; tl = g_wql; break;
        case 1: W = Wk; th = g_wkh; tl = g_wkl; break;
        case 2: W = Wv; th = g_wvh; tl = g_wvl; break;
        default: W = Wo; th = g_woh; tl = g_wol; break;
    }
    const int tx = threadIdx.x & 31, ty = threadIdx.x >> 5;
    const int tR = (bxx & 7) * 32, tC = (bxx >> 3) * 32;
    #pragma unroll
    for (int j = 0; j < 4; j++)
        tile[ty + j * 8][tx] = W[(tR + ty + j * 8) * DD + tC + tx];
    __syncthreads();
    #pragma unroll
    for (int j = 0; j < 4; j++) {
        int n = tC + ty + j * 8, k = tR + tx;
        float w = tile[tx][ty + j * 8];
        __nv_bfloat16 h = __float2bfloat16(w);
        th[n * DD + k] = h;
        tl[n * DD + k] = __float2bfloat16(w - __bfloat162float(h));
    }
}

// ================= projection GEMM: 64x256 tiles, fp32 A fused split in-kernel ==========
#define PSTR 40
#define MA_TILE (64 * PSTR * 2)       // 5120 B
#define MB_TILE (256 * PSTR * 2)      // 20480 B
#define MSTAGE (2 * MA_TILE + 2 * MB_TILE)   // 51200 B
#define MLP_SMEM (2 * MSTAGE)                // 102400 B
#define NCH 8

__global__ void __launch_bounds__(256, 2) proj_kernel(
    const float* __restrict__ Qf, const float* __restrict__ Kf,
    const float* __restrict__ bq, const float* __restrict__ bk,
    const float* __restrict__ bv, const int* __restrict__ lengths)
{
    extern __shared__ char smc[];
    const int tid = threadIdx.x, wid = tid >> 5, lane = tid & 31;
    const int brow = blockIdx.x * 64;
    const int wm = wid & 1, wn = wid >> 1;

    const float* Af;
    const __nv_bfloat16 *Bh_, *Bl_;
    const float *bias;
    __nv_bfloat16 *Ch, *Cl;
    switch (blockIdx.y) {
        case 0:  Af = Qf; Bh_ = g_wqh; Bl_ = g_wql; bias = bq; Ch = g_aqh; Cl = g_aql; break;
        case 1:  Af = Kf; Bh_ = g_wkh; Bl_ = g_wkl; bias = bk; Ch = g_akh; Cl = g_akl; break;
        default: Af = Kf; Bh_ = g_wvh; Bl_ = g_wvl; bias = bv; Ch = g_avh; Cl = g_avl; break;
    }

    const int blen = lengths[brow >> 10];
    if ((brow & 1023) >= blen) {
        uint4 zu = make_uint4(0u, 0u, 0u, 0u);
        #pragma unroll
        for (int i = 0; i < 8; i++) {
            int idx = tid + i * 256;
            int r = idx >> 5, half = (idx >> 4) & 1, c8 = idx & 15;
            __nv_bfloat16* dst = half ? Cl : Ch;
            *(uint4*)&dst[(size_t)(brow + r) * DD + c8 * 8] = zu;
        }
        return;
    }

    const uint32_t sbu = (uint32_t)__cvta_generic_to_shared(smc);
    const int ldr4 = tid >> 2;      // row 0..63
    const int ldc4 = tid & 3;       // 8-col group

    float4 pa0, pa1;                // fp32 A prefetch registers
    auto lda = [&](int ch) {
        size_t ga = (size_t)(brow + ldr4) * DD + ch * 32 + ldc4 * 8;
        pa0 = *(const float4*)(Af + ga);
        pa1 = *(const float4*)(Af + ga + 4);
    };
    auto cvt_sts = [&](int st) {    // split regs -> Ah/Al of stage st
        uint32_t off = (uint32_t)(ldr4 * PSTR + ldc4 * 8) * 2u;
        uint4 hv, lv;
        uint32_t h0 = packbf(pa0.x, pa0.y); hv.x = h0;
        uint32_t h1 = packbf(pa0.z, pa0.w); hv.y = h1;
        uint32_t h2 = packbf(pa1.x, pa1.y); hv.z = h2;
        uint32_t h3 = packbf(pa1.z, pa1.w); hv.w = h3;
        lv.x = packbf(pa0.x - bflo_f(h0), pa0.y - bfhi_f(h0));
        lv.y = packbf(pa0.z - bflo_f(h1), pa0.w - bfhi_f(h1));
        lv.z = packbf(pa1.x - bflo_f(h2), pa1.y - bfhi_f(h2));
        lv.w = packbf(pa1.z - bflo_f(h3), pa1.w - bfhi_f(h3));
        *(uint4*)(smc + st * MSTAGE + off) = hv;
        *(uint4*)(smc + st * MSTAGE + MA_TILE + off) = lv;
    };
    auto ldb = [&](int ch, int st) {
        const int kc0 = ch * 32;
        const uint32_t s0 = sbu + st * MSTAGE;
        #pragma unroll
        for (int i = 0; i < 4; i++) {
            int r = ldr4 + i * 64;
            size_t gb = (size_t)r * DD + kc0 + ldc4 * 8;
            uint32_t so = (uint32_t)(r * PSTR + ldc4 * 8) * 2u;
            cpa16(s0 + 2 * MA_TILE + so, Bh_ + gb);
            cpa16(s0 + 2 * MA_TILE + MB_TILE + so, Bl_ + gb);
        }
    };

    float acc[2][8][4];
    #pragma unroll
    for (int i = 0; i < 2; i++)
        #pragma unroll
        for (int j = 0; j < 8; j++)
            #pragma unroll
            for (int p = 0; p < 4; p++) acc[i][j][p] = 0.f;

    const int aRow = wm * 32 + (lane & 15);
    const int aK   = (lane >> 4) * 8;
    const int bRow = wn * 64 + (lane & 7) + (lane >> 4) * 8;
    const int bK   = ((lane >> 3) & 1) * 8;

    ldb(0, 0);
    cpa_commit();
    lda(0);
    cvt_sts(0);          // stalls on first LDG only

    for (int ch = 0; ch < NCH; ch++) {
        const int st = ch & 1;
        if (ch < NCH - 1) { ldb(ch + 1, st ^ 1); cpa_commit(); lda(ch + 1); }
        if (ch < NCH - 1) cpa_wait<1>(); else cpa_wait<0>();
        __syncthreads();

        const uint32_t stb = sbu + st * MSTAGE;
        const uint32_t bAh = stb, bAl = stb + MA_TILE;
        const uint32_t bBh = stb + 2 * MA_TILE, bBl = bBh + MB_TILE;

        #pragma unroll
        for (int ks = 0; ks < 2; ks++) {
            const int kk = ks * 16;
            uint32_t ah[2][4], al[2][4], bh[4][4], bl[4][4];
            #pragma unroll
            for (int mi = 0; mi < 2; mi++) {
                uint32_t off = (uint32_t)((aRow + mi * 16) * PSTR + kk + aK) * 2u;
                ldmx4(ah[mi], bAh + off);
                ldmx4(al[mi], bAl + off);
            }
            #pragma unroll
            for (int n2 = 0; n2 < 4; n2++) {
                uint32_t off = (uint32_t)((bRow + n2 * 16) * PSTR + kk + bK) * 2u;
                ldmx4(bh[n2], bBh + off);
                ldmx4(bl[n2], bBl + off);
            }
            #pragma unroll
            for (int mi = 0; mi < 2; mi++)
                #pragma unroll
                for (int ni = 0; ni < 8; ni++) {
                    uint32_t bh0 = bh[ni >> 1][(ni & 1) * 2], bh1 = bh[ni >> 1][(ni & 1) * 2 + 1];
                    uint32_t bl0 = bl[ni >> 1][(ni & 1) * 2], bl1 = bl[ni >> 1][(ni & 1) * 2 + 1];
                    mma_bf16(acc[mi][ni], ah[mi], bh0, bh1);
                    mma_bf16(acc[mi][ni], ah[mi], bl0, bl1);
                    mma_bf16(acc[mi][ni], al[mi], bh0, bh1);
                }
        }
        if (ch < NCH - 1) cvt_sts(st ^ 1);   // LDG has had the MMA phase to land
        __syncthreads();
    }

    #pragma unroll
    for (int mi = 0; mi < 2; mi++) {
        int r0 = brow + wm * 32 + mi * 16 + (lane >> 2);
        int r1 = r0 + 8;
        #pragma unroll
        for (int ni = 0; ni < 8; ni++) {
            int col = wn * 64 + ni * 8 + (lane & 3) * 2;
            float b0 = bias[col], b1 = bias[col + 1];
            float c0 = acc[mi][ni][0] + b0, c1 = acc[mi][ni][1] + b1;
            float c2 = acc[mi][ni][2] + b0, c3 = acc[mi][ni][3] + b1;
            if ((r0 & 1023) >= blen) { c0 = 0.f; c1 = 0.f; }
            if ((r1 & 1023) >= blen) { c2 = 0.f; c3 = 0.f; }
            uint32_t h0 = packbf(c0, c1), h1 = packbf(c2, c3);
            uint32_t l0 = packbf(c0 - bflo_f(h0), c1 - bfhi_f(h0));
            uint32_t l1 = packbf(c2 - bflo_f(h1), c3 - bfhi_f(h1));
            *(uint32_t*)&Ch[(size_t)r0 * DD + col] = h0;
            *(uint32_t*)&Cl[(size_t)r0 * DD + col] = l0;
            *(uint32_t*)&Ch[(size_t)r1 * DD + col] = h1;
            *(uint32_t*)&Cl[(size_t)r1 * DD + col] = l1;
        }
    }
}

// ================= fused MLP GEMM + residual + relu + LayerNorm1 → d_out (verified) =====
__global__ void __launch_bounds__(256, 2) mlp_ln_kernel(
    const float* __restrict__ bo, const float* __restrict__ g1,
    const float* __restrict__ b1, float* __restrict__ out)
{
    extern __shared__ char smc[];
    const int tid = threadIdx.x, wid = tid >> 5, lane = tid & 31;
    const int brow = blockIdx.x * 64;
    const int wm = wid & 1, wn = wid >> 1;

    const uint32_t sbu = (uint32_t)__cvta_generic_to_shared(smc);
    const int ldr4 = tid >> 2;
    const int ldc4 = tid & 3;

    auto load_chunk = [&](int ch, int st) {
        const int kc0 = ch * 32;
        const uint32_t s0 = sbu + st * MSTAGE;
        {
            size_t ga = (size_t)(brow + ldr4) * DD + kc0 + ldc4 * 8;
            uint32_t so = (uint32_t)(ldr4 * PSTR + ldc4 * 8) * 2u;
            cpa16(s0 + so, g_th + ga);
            cpa16(s0 + MA_TILE + so, g_tl + ga);
        }
        #pragma unroll
        for (int i = 0; i < 4; i++) {
            int r = ldr4 + i * 64;
            size_t gb = (size_t)r * DD + kc0 + ldc4 * 8;
            uint32_t so = (uint32_t)(r * PSTR + ldc4 * 8) * 2u;
            cpa16(s0 + 2 * MA_TILE + so, g_woh + gb);
            cpa16(s0 + 2 * MA_TILE + MB_TILE + so, g_wol + gb);
        }
    };

    float acc[2][8][4];
    #pragma unroll
    for (int i = 0; i < 2; i++)
        #pragma unroll
        for (int j = 0; j < 8; j++)
            #pragma unroll
            for (int p = 0; p < 4; p++) acc[i][j][p] = 0.f;

    const int aRow = wm * 32 + (lane & 15);
    const int aK   = (lane >> 4) * 8;
    const int bRow = wn * 64 + (lane & 7) + (lane >> 4) * 8;
    const int bK   = ((lane >> 3) & 1) * 8;

    load_chunk(0, 0);
    cpa_commit();

    for (int ch = 0; ch < NCH; ch++) {
        if (ch < NCH - 1) { load_chunk(ch + 1, (ch + 1) & 1); cpa_commit(); }
        if (ch < NCH - 1) cpa_wait<1>(); else cpa_wait<0>();
        __syncthreads();

        const uint32_t stb = sbu + (ch & 1) * MSTAGE;
        const uint32_t bAh = stb, bAl = stb + MA_TILE;
        const uint32_t bBh = stb + 2 * MA_TILE, bBl = bBh + MB_TILE;

        #pragma unroll
        for (int ks = 0; ks < 2; ks++) {
            const int kk = ks * 16;
            uint32_t ah[2][4], al[2][4], bh[4][4], bl[4][4];
            #pragma unroll
            for (int mi = 0; mi < 2; mi++) {
                uint32_t off = (uint32_t)((aRow + mi * 16) * PSTR + kk + aK) * 2u;
                ldmx4(ah[mi], bAh + off);
                ldmx4(al[mi], bAl + off);
            }
            #pragma unroll
            for (int n2 = 0; n2 < 4; n2++) {
                uint32_t off = (uint32_t)((bRow + n2 * 16) * PSTR + kk + bK) * 2u;
                ldmx4(bh[n2], bBh + off);
                ldmx4(bl[n2], bBl + off);
            }
            #pragma unroll
            for (int mi = 0; mi < 2; mi++)
                #pragma unroll
                for (int ni = 0; ni < 8; ni++) {
                    uint32_t bh0 = bh[ni >> 1][(ni & 1) * 2], bh1 = bh[ni >> 1][(ni & 1) * 2 + 1];
                    uint32_t bl0 = bl[ni >> 1][(ni & 1) * 2], bl1 = bl[ni >> 1][(ni & 1) * 2 + 1];
                    mma_bf16(acc[mi][ni], ah[mi], bh0, bh1);
                    mma_bf16(acc[mi][ni], ah[mi], bl0, bl1);
                    mma_bf16(acc[mi][ni], al[mi], bh0, bh1);
                }
        }
        __syncthreads();
    }

    float* sums = (float*)smc;
    float* sqs  = sums + 64 * 4;

    #pragma unroll
    for (int mi = 0; mi < 2; mi++) {
        int r0 = brow + wm * 32 + mi * 16 + (lane >> 2);
        int r1 = r0 + 8;
        float s0 = 0.f, q0 = 0.f, s1 = 0.f, q1 = 0.f;
        #pragma unroll
        for (int ni = 0; ni < 8; ni++) {
            int col = wn * 64 + ni * 8 + (lane & 3) * 2;
            float b0 = bo[col], b1v = bo[col + 1];
            uint32_t xh0 = *(const uint32_t*)&g_th[(size_t)r0 * DD + col];
            uint32_t xl0 = *(const uint32_t*)&g_tl[(size_t)r0 * DD + col];
            uint32_t xh1 = *(const uint32_t*)&g_th[(size_t)r1 * DD + col];
            uint32_t xl1 = *(const uint32_t*)&g_tl[(size_t)r1 * DD + col];
            float c0 = (bflo_f(xh0) + bflo_f(xl0)) + fmaxf(acc[mi][ni][0] + b0, 0.f);
            float c1 = (bfhi_f(xh0) + bfhi_f(xl0)) + fmaxf(acc[mi][ni][1] + b1v, 0.f);
            float c2 = (bflo_f(xh1) + bflo_f(xl1)) + fmaxf(acc[mi][ni][2] + b0, 0.f);
            float c3 = (bfhi_f(xh1) + bfhi_f(xl1)) + fmaxf(acc[mi][ni][3] + b1v, 0.f);
            acc[mi][ni][0] = c0; acc[mi][ni][1] = c1;
            acc[mi][ni][2] = c2; acc[mi][ni][3] = c3;
            s0 += c0 + c1; q0 += c0 * c0 + c1 * c1;
            s1 += c2 + c3; q1 += c2 * c2 + c3 * c3;
        }
        s0 += __shfl_xor_sync(0xFFFFFFFFu, s0, 1); s0 += __shfl_xor_sync(0xFFFFFFFFu, s0, 2);
        q0 += __shfl_xor_sync(0xFFFFFFFFu, q0, 1); q0 += __shfl_xor_sync(0xFFFFFFFFu, q0, 2);
        s1 += __shfl_xor_sync(0xFFFFFFFFu, s1, 1); s1 += __shfl_xor_sync(0xFFFFFFFFu, s1, 2);
        q1 += __shfl_xor_sync(0xFFFFFFFFu, q1, 1); q1 += __shfl_xor_sync(0xFFFFFFFFu, q1, 2);
        if ((lane & 3) == 0) {
            int lr = wm * 32 + mi * 16 + (lane >> 2);
            sums[lr * 4 + wn] = s0; sqs[lr * 4 + wn] = q0;
            sums[(lr + 8) * 4 + wn] = s1; sqs[(lr + 8) * 4 + wn] = q1;
        }
    }
    __syncthreads();

    #pragma unroll
    for (int mi = 0; mi < 2; mi++) {
        int lr0 = wm * 32 + mi * 16 + (lane >> 2);
        int lr1 = lr0 + 8;
        float mu0 = (sums[lr0*4+0] + sums[lr0*4+1] + sums[lr0*4+2] + sums[lr0*4+3]) * (1.f/256.f);
        float mu1 = (sums[lr1*4+0] + sums[lr1*4+1] + sums[lr1*4+2] + sums[lr1*4+3]) * (1.f/256.f);
        float v0 = (sqs[lr0*4+0] + sqs[lr0*4+1] + sqs[lr0*4+2] + sqs[lr0*4+3]) * (1.f/256.f) - mu0 * mu0;
        float v1 = (sqs[lr1*4+0] + sqs[lr1*4+1] + sqs[lr1*4+2] + sqs[lr1*4+3]) * (1.f/256.f) - mu1 * mu1;
        float r0s = rsqrtf(v0 + 1e-5f);
        float r1s = rsqrtf(v1 + 1e-5f);
        int gr0 = brow + lr0, gr1 = brow + lr1;
        #pragma unroll
        for (int ni = 0; ni < 8; ni++) {
            int col = wn * 64 + ni * 8 + (lane & 3) * 2;
            float2 gg = *(const float2*)&g1[col];
            float2 bb = *(const float2*)&b1[col];
            float2 o0, o1;
            o0.x = (acc[mi][ni][0] - mu0) * r0s * gg.x + bb.x;
            o0.y = (acc[mi][ni][1] - mu0) * r0s * gg.y + bb.y;
            o1.x = (acc[mi][ni][2] - mu1) * r1s * gg.x + bb.x;
            o1.y = (acc[mi][ni][3] - mu1) * r1s * gg.y + bb.y;
            *(float2*)&out[(size_t)gr0 * DD + col] = o0;
            *(float2*)&out[(size_t)gr1 * DD + col] = o1;
        }
    }
}

// ================= HMMA attention (round-15 verified: full bf16x3 S restored) ===========
#define QSTR 56
#define KSTR 56
#define VSTR2 40
#define SM_QH 0
#define SM_QL (SM_QH + 128*QSTR*2)      // 14336
#define SM_ST0 (SM_QL + 128*QSTR*2)     // 28672
#define KBYTES (64*KSTR*2)              // 7168
#define VBYTES (64*VSTR2*2)             // 5120
#define STAGEA (2*KBYTES + 2*VBYTES)    // 24576
#define SM_ATTN2 (SM_ST0 + 2*STAGEA)    // 77824

__global__ void __launch_bounds__(256) attn_hmma_kernel(
    const int* __restrict__ lengths, float* __restrict__ o)
{
    extern __shared__ char smc[];
    const int qt = blockIdx.x, h = blockIdx.y, b = blockIdx.z;
    const int len = lengths[b];
    const int tid = threadIdx.x, w = tid >> 5, lane = tid & 31;

    if (qt * 128 >= len) {
        float4 z = make_float4(0.f, 0.f, 0.f, 0.f);
        #pragma unroll
        for (int i = 0; i < 4; i++) {
            int idx = tid + i * 256;
            int r = idx >> 3, c4 = idx & 7;
            *(float4*)&o[((size_t)b * NN + qt * 128 + r) * DD + h * HD + c4 * 4] = z;
        }
        return;
    }

    const uint32_t sb = (uint32_t)__cvta_generic_to_shared(smc);

    const int ldr = tid >> 2, ldc4 = tid & 3;
    auto load_tile = [&](int m0, int st) {
        int row = m0 + ldr; if (row >= len) row = len - 1;
        size_t g = ((size_t)b * NN + row) * DD + h * HD + ldc4 * 8;
        uint32_t s0 = sb + SM_ST0 + st * STAGEA;
        cpa16(s0 + (uint32_t)(ldr * KSTR + ldc4 * 8) * 2u,           g_akh + g);
        cpa16(s0 + KBYTES + (uint32_t)(ldr * KSTR + ldc4 * 8) * 2u,  g_akl + g);
        cpa16(s0 + 2*KBYTES + (uint32_t)(ldr * VSTR2 + ldc4 * 8) * 2u,          g_avh + g);
        cpa16(s0 + 2*KBYTES + VBYTES + (uint32_t)(ldr * VSTR2 + ldc4 * 8) * 2u, g_avl + g);
    };

    load_tile(0, 0);
    cpa_commit();

    {   // Q tile (128 x 32) hi/lo
        const size_t gq = ((size_t)b * NN + qt * 128) * DD + h * HD;
        #pragma unroll
        for (int i = 0; i < 2; i++) {
            int idx = tid + i * 256;
            int r = idx >> 2, c4 = idx & 3;
            *(uint4*)(smc + SM_QH + (r * QSTR + c4 * 8) * 2) = *(const uint4*)(g_aqh + gq + (size_t)r * DD + c4 * 8);
            *(uint4*)(smc + SM_QL + (r * QSTR + c4 * 8) * 2) = *(const uint4*)(g_aql + gq + (size_t)r * DD + c4 * 8);
        }
    }
    __syncthreads();

    uint32_t qfh[2][4], qfl[2][4];
    {
        int row = w * 16 + (lane & 15);
        #pragma unroll
        for (int kt = 0; kt < 2; kt++) {
            uint32_t off = (uint32_t)(row * QSTR + kt * 16 + (lane >> 4) * 8) * 2u;
            ldmx4(qfh[kt], sb + SM_QH + off);
            ldmx4(qfl[kt], sb + SM_QL + off);
        }
    }

    float ofA[4][4], ofB[4][4];
    #pragma unroll
    for (int i = 0; i < 4; i++)
        #pragma unroll
        for (int p = 0; p < 4; p++) { ofA[i][p] = 0.f; ofB[i][p] = 0.f; }
    float es0a = 0.f, es0b = 0.f, es1a = 0.f, es1b = 0.f;

    const int kRow = (lane & 7) + ((lane >> 4) << 3);
    const int kColHalf = ((lane >> 3) & 1) * 8;
    const int vRow = lane & 15;
    const int vCol = (lane >> 4) * 8;

    int st = 0;
    for (int m0 = 0; m0 < len; m0 += 64, st ^= 1) {
        cpa_wait<0>();
        __syncthreads();
        if (m0 + 64 < len) { load_tile(m0 + 64, st ^ 1); cpa_commit(); }

        const uint32_t bKH = sb + SM_ST0 + st * STAGEA;
        const uint32_t bKL = bKH + KBYTES;
        const uint32_t bVH = bKH + 2 * KBYTES;
        const uint32_t bVL = bVH + VBYTES;

        float sf[8][4];
        #pragma unroll
        for (int i = 0; i < 8; i++)
            #pragma unroll
            for (int p = 0; p < 4; p++) sf[i][p] = 0.f;
        #pragma unroll
        for (int kt = 0; kt < 2; kt++) {
            #pragma unroll
            for (int g2 = 0; g2 < 4; g2++) {
                uint32_t off = (uint32_t)((g2 * 16 + kRow) * KSTR + kt * 16 + kColHalf) * 2u;
                uint32_t kbh[4], kbl[4];
                ldmx4(kbh, bKH + off);
                ldmx4(kbl, bKL + off);
                mma_bf16(sf[g2*2],   qfh[kt], kbh[0], kbh[1]);
                mma_bf16(sf[g2*2],   qfh[kt], kbl[0], kbl[1]);
                mma_bf16(sf[g2*2],   qfl[kt], kbh[0], kbh[1]);
                mma_bf16(sf[g2*2+1], qfh[kt], kbh[2], kbh[3]);
                mma_bf16(sf[g2*2+1], qfh[kt], kbl[2], kbl[3]);
                mma_bf16(sf[g2*2+1], qfl[kt], kbh[2], kbh[3]);
            }
        }

        uint32_t ph[8], phb[8], pl[8], plb[8];
        if (m0 + 64 <= len) {
            #pragma unroll
            for (int ni = 0; ni < 8; ni++) {
                float e0 = __expf(sf[ni][0] * 0.0625f);
                float e1 = __expf(sf[ni][1] * 0.0625f);
                float e2 = __expf(sf[ni][2] * 0.0625f);
                float e3 = __expf(sf[ni][3] * 0.0625f);
                if (ni & 1) { es0b += e0 + e1; es1b += e2 + e3; }
                else        { es0a += e0 + e1; es1a += e2 + e3; }
                uint32_t h0 = packbf(e0, e1), h1 = packbf(e2, e3);
                ph[ni] = h0; phb[ni] = h1;
                pl[ni]  = packbf(e0 - bflo_f(h0), e1 - bfhi_f(h0));
                plb[ni] = packbf(e2 - bflo_f(h1), e3 - bfhi_f(h1));
            }
        } else {
            #pragma unroll
            for (int ni = 0; ni < 8; ni++) {
                int k0 = m0 + ni * 8 + ((lane & 3) << 1);
                float e0 = (k0     < len) ? __expf(sf[ni][0] * 0.0625f) : 0.f;
                float e1 = (k0 + 1 < len) ? __expf(sf[ni][1] * 0.0625f) : 0.f;
                float e2 = (k0     < len) ? __expf(sf[ni][2] * 0.0625f) : 0.f;
                float e3 = (k0 + 1 < len) ? __expf(sf[ni][3] * 0.0625f) : 0.f;
                if (ni & 1) { es0b += e0 + e1; es1b += e2 + e3; }
                else        { es0a += e0 + e1; es1a += e2 + e3; }
                uint32_t h0 = packbf(e0, e1), h1 = packbf(e2, e3);
                ph[ni] = h0; phb[ni] = h1;
                pl[ni]  = packbf(e0 - bflo_f(h0), e1 - bfhi_f(h0));
                plb[ni] = packbf(e2 - bflo_f(h1), e3 - bfhi_f(h1));
            }
        }

        #pragma unroll
        for (int kt2 = 0; kt2 < 4; kt2++) {
            uint32_t pa_h[4] = { ph[2*kt2], phb[2*kt2], ph[2*kt2+1], phb[2*kt2+1] };
            uint32_t pa_l[4] = { pl[2*kt2], plb[2*kt2], pl[2*kt2+1], plb[2*kt2+1] };
            #pragma unroll
            for (int g2 = 0; g2 < 2; g2++) {
                uint32_t off = (uint32_t)((kt2 * 16 + vRow) * VSTR2 + g2 * 16 + vCol) * 2u;
                uint32_t vbh[4], vbl[4];
                ldmx4t(vbh, bVH + off);
                ldmx4t(vbl, bVL + off);
                mma_bf16(ofA[g2*2],   pa_h, vbh[0], vbh[1]);
                mma_bf16(ofB[g2*2],   pa_h, vbl[0], vbl[1]);
                mma_bf16(ofA[g2*2+1], pa_h, vbh[2], vbh[3]);
                mma_bf16(ofB[g2*2+1], pa_h, vbl[2], vbl[3]);
                if (kt2 & 1) {
                    mma_bf16(ofA[g2*2],   pa_l, vbh[0], vbh[1]);
                    mma_bf16(ofB[g2*2+1], pa_l, vbh[2], vbh[3]);
                } else {
                    mma_bf16(ofB[g2*2],   pa_l, vbh[0], vbh[1]);
                    mma_bf16(ofA[g2*2+1], pa_l, vbh[2], vbh[3]);
                }
            }
        }
    }

    float es0 = es0a + es0b, es1 = es1a + es1b;
    es0 += __shfl_xor_sync(0xFFFFFFFFu, es0, 1);
    es0 += __shfl_xor_sync(0xFFFFFFFFu, es0, 2);
    es1 += __shfl_xor_sync(0xFFFFFFFFu, es1, 1);
    es1 += __shfl_xor_sync(0xFFFFFFFFu, es1, 2);
    const float inv0 = 1.f / (es0 + 1e-15f);
    const float inv1 = 1.f / (es1 + 1e-15f);

    const int n0 = qt * 128 + w * 16 + (lane >> 2);
    const int n1 = n0 + 8;
    const bool a0 = n0 < len, a1 = n1 < len;
    const int r0l = w * 16 + (lane >> 2);
    #pragma unroll
    for (int ni = 0; ni < 4; ni++) {
        int ci = ni * 8 + ((lane & 3) << 1);
        int col = h * HD + ci;
        uint32_t uh0 = *(uint32_t*)(smc + SM_QH + (r0l * QSTR + ci) * 2);
        uint32_t ul0 = *(uint32_t*)(smc + SM_QL + (r0l * QSTR + ci) * 2);
        uint32_t uh1 = *(uint32_t*)(smc + SM_QH + ((r0l + 8) * QSTR + ci) * 2);
        uint32_t ul1 = *(uint32_t*)(smc + SM_QL + ((r0l + 8) * QSTR + ci) * 2);
        float2 o0, o1;
        o0.x = a0 ? (bflo_f(uh0) + bflo_f(ul0) + (ofA[ni][0] + ofB[ni][0]) * inv0) : 0.f;
        o0.y = a0 ? (bfhi_f(uh0) + bfhi_f(ul0) + (ofA[ni][1] + ofB[ni][1]) * inv0) : 0.f;
        o1.x = a1 ? (bflo_f(uh1) + bflo_f(ul1) + (ofA[ni][2] + ofB[ni][2]) * inv1) : 0.f;
        o1.y = a1 ? (bfhi_f(uh1) + bfhi_f(ul1) + (ofA[ni][3] + ofB[ni][3]) * inv1) : 0.f;
        *(float2*)&o[((size_t)b * NN + n0) * DD + col] = o0;
        *(float2*)&o[((size_t)b * NN + n1) * DD + col] = o1;
    }
}

// ---------------- warp-per-row LayerNorm0 (verified round-15) ----------------
__global__ void __launch_bounds__(256) ln_kernel(
    const float* __restrict__ x, const float* __restrict__ g,
    const float* __restrict__ b,
    __nv_bfloat16* __restrict__ yh, __nv_bfloat16* __restrict__ yl)
{
    const int row = blockIdx.x * 8 + (threadIdx.x >> 5);
    const int lane = threadIdx.x & 31;
    const int c0 = lane * 8;

    float4 v0 = *(const float4*)&x[(size_t)row * DD + c0];
    float4 v1 = *(const float4*)&x[(size_t)row * DD + c0 + 4];

    float s = ((v0.x + v0.y) + (v0.z + v0.w)) + ((v1.x + v1.y) + (v1.z + v1.w));
    float q = ((v0.x*v0.x + v0.y*v0.y) + (v0.z*v0.z + v0.w*v0.w))
            + ((v1.x*v1.x + v1.y*v1.y) + (v1.z*v1.z + v1.w*v1.w));
    #pragma unroll
    for (int o = 16; o > 0; o >>= 1) {
        s += __shfl_xor_sync(0xFFFFFFFFu, s, o);
        q += __shfl_xor_sync(0xFFFFFFFFu, q, o);
    }
    const float mu = s * (1.f / 256.f);
    const float var = q * (1.f / 256.f) - mu * mu;
    const float r = rsqrtf(var + 1e-5f);

    float4 gg0 = *(const float4*)&g[c0], gg1 = *(const float4*)&g[c0 + 4];
    float4 bb0 = *(const float4*)&b[c0], bb1 = *(const float4*)&b[c0 + 4];
    float out[8];
    out[0] = (v0.x - mu) * r * gg0.x + bb0.x; out[1] = (v0.y - mu) * r * gg0.y + bb0.y;
    out[2] = (v0.z - mu) * r * gg0.z + bb0.z; out[3] = (v0.w - mu) * r * gg0.w + bb0.w;
    out[4] = (v1.x - mu) * r * gg1.x + bb1.x; out[5] = (v1.y - mu) * r * gg1.y + bb1.y;
    out[6] = (v1.z - mu) * r * gg1.z + bb1.z; out[7] = (v1.w - mu) * r * gg1.w + bb1.w;

    uint4 hv, lv;
    uint32_t h0 = packbf(out[0], out[1]); hv.x = h0;
    uint32_t h1 = packbf(out[2], out[3]); hv.y = h1;
    uint32_t h2 = packbf(out[4], out[5]); hv.z = h2;
    uint32_t h3 = packbf(out[6], out[7]); hv.w = h3;
    lv.x = packbf(out[0] - bflo_f(h0), out[1] - bfhi_f(h0));
    lv.y = packbf(out[2] - bflo_f(h1), out[3] - bfhi_f(h1));
    lv.z = packbf(out[4] - bflo_f(h2), out[5] - bfhi_f(h2));
    lv.w = packbf(out[6] - bflo_f(h3), out[7] - bfhi_f(h3));
    *(uint4*)&yh[(size_t)row * DD + c0] = hv;
    *(uint4*)&yl[(size_t)row * DD + c0] = lv;
}

// ---------------- launch ----------------
extern "C" void kernel_launch(void* const* d_in, const int* in_sizes, int n_in,
                              void* d_out, int out_size)
{
    const float* Q       = (const float*)d_in[0];
    const float* K       = (const float*)d_in[1];
    const int*   lengths = (const int*)  d_in[2];
    const float* Wq      = (const float*)d_in[3];
    const float* bq      = (const float*)d_in[4];
    const float* Wk      = (const float*)d_in[5];
    const float* bk      = (const float*)d_in[6];
    const float* Wv      = (const float*)d_in[7];
    const float* bv      = (const float*)d_in[8];
    const float* Wo      = (const float*)d_in[9];
    const float* bo      = (const float*)d_in[10];
    const float* g0      = (const float*)d_in[11];
    const float* b0      = (const float*)d_in[12];
    const float* g1      = (const float*)d_in[13];
    const float* b1      = (const float*)d_in[14];

    float *so;
    cudaGetSymbolAddress((void**)&so, g_o);
    __nv_bfloat16 *th, *tl;
    cudaGetSymbolAddress((void**)&th, g_th);
    cudaGetSymbolAddress((void**)&tl, g_tl);

    static int cfg = 0;
    if (!cfg) {
        cudaFuncSetAttribute(proj_kernel, cudaFuncAttributeMaxDynamicSharedMemorySize, MLP_SMEM);
        cudaFuncSetAttribute(mlp_ln_kernel, cudaFuncAttributeMaxDynamicSharedMemorySize, MLP_SMEM);
        cudaFuncSetAttribute(attn_hmma_kernel, cudaFuncAttributeMaxDynamicSharedMemorySize, SM_ATTN2);
        cfg = 1;
    }

    prep_kernel<<<256, 256>>>(Wq, Wk, Wv, Wo);

    proj_kernel<<<dim3(ROWS / 64, 3), 256, MLP_SMEM>>>(Q, K, bq, bk, bv, lengths);

    attn_hmma_kernel<<<dim3(NN / 128, HH, BB), 256, SM_ATTN2>>>(lengths, so);

    ln_kernel<<<ROWS / 8, 256>>>(so, g0, b0, th, tl);

    mlp_ln_kernel<<<ROWS / 64, 256, MLP_SMEM>>>(bo, g1, b1, (float*)d_out);
}